// round 1
// baseline (speedup 1.0000x reference)
#include <cuda_runtime.h>

#define EPS 0.001f

// Each thread processes 4 consecutive rows (6 float4 loads = 96B contiguous,
// 2 float4 stores = 32B), grid-stride over "quads". Weights (53 floats) are
// hoisted into registers once per thread, amortized over all iterations.
__device__ __forceinline__ void compute_row(
    const float in[6],
    const float w1[6][2], const float vb1[6],
    const float w2[2][6], const float vb2[2],
    const float w3[2][6], const float vb3[2],
    const float w4[6], const float vb4,
    float& t0, float& t1)
{
    const float q0 = in[0], q1 = in[1];
    const float qd0 = in[2], qd1 = in[3];
    const float qdd0 = in[4], qdd1 = in[5];

    // h1 = relu(W1 q + b1), hp = mask
    float h[6], hp[6];
#pragma unroll
    for (int j = 0; j < 6; j++) {
        float z = fmaf(w1[j][0], q0, fmaf(w1[j][1], q1, vb1[j]));
        h[j] = fmaxf(z, 0.0f);
        hp[j] = (z > 0.0f) ? 1.0f : 0.0f;
    }

    // g = W2 h + b2 ; pre-relu s3 for ld ; lo = W4 h + b4
    float g0 = vb2[0], g1 = vb2[1];
    float s30 = vb3[0], s31 = vb3[1];
    float lo = vb4;
#pragma unroll
    for (int j = 0; j < 6; j++) {
        g0 = fmaf(w2[0][j], h[j], g0);
        g1 = fmaf(w2[1][j], h[j], g1);
        s30 = fmaf(w3[0][j], h[j], s30);
        s31 = fmaf(w3[1][j], h[j], s31);
        lo = fmaf(w4[j], h[j], lo);
    }
    const float a = fmaxf(s30, 0.0f);   // ld0
    const float b = fmaxf(s31, 0.0f);   // ld1
    const float c = lo;                 // lo (no relu)
    const float m0 = (s30 > 0.0f) ? 1.0f : 0.0f;
    const float m1 = (s31 > 0.0f) ? 1.0f : 0.0f;

    // dld_dq[i][k] = m_i * sum_j W3[i][j]*hp[j]*W1[j][k]
    // dlo_dq[k]    =       sum_j W4[j]   *hp[j]*W1[j][k]
    float d00 = 0.f, d01 = 0.f, d10 = 0.f, d11 = 0.f, e0 = 0.f, e1 = 0.f;
#pragma unroll
    for (int j = 0; j < 6; j++) {
        float u0 = hp[j] * w1[j][0];
        float u1 = hp[j] * w1[j][1];
        d00 = fmaf(w3[0][j], u0, d00);
        d01 = fmaf(w3[0][j], u1, d01);
        d10 = fmaf(w3[1][j], u0, d10);
        d11 = fmaf(w3[1][j], u1, d11);
        e0  = fmaf(w4[j],    u0, e0);
        e1  = fmaf(w4[j],    u1, e1);
    }
    d00 *= m0; d01 *= m0; d10 *= m1; d11 *= m1;

    // time derivatives
    const float da = fmaf(d00, qd0, d01 * qd1);   // dld_dt[0]
    const float db = fmaf(d10, qd0, d11 * qd1);   // dld_dt[1]
    const float dc = fmaf(e0,  qd0, e1  * qd1);   // dlo_dt

    // H q_ddot = L^T (L q_ddot) + eps q_ddot,  L = [[a,0],[c,b]]
    const float Lq0 = a * qdd0;
    const float Lq1 = fmaf(c, qdd0, b * qdd1);
    const float Hq0 = fmaf(a, Lq0, fmaf(c, Lq1, EPS * qdd0));
    const float Hq1 = fmaf(b, Lq1, EPS * qdd1);

    // dH_dt = [[2 a da, a dc + c da],[a dc + c da, 2(c dc + b db)]]
    const float dh01 = fmaf(a, dc, c * da);
    const float dHq0 = fmaf(2.0f * a * da, qd0, dh01 * qd1);
    const float dHq1 = fmaf(dh01, qd0, 2.0f * fmaf(c, dc, b * db) * qd1);

    // quad_i = 2 * (B_i^T qd) . (L^T qd),  B_i = [[d0i,0],[e_i,d1i]]
    const float Ltq0 = fmaf(a, qd0, c * qd1);
    const float Ltq1 = b * qd1;
    const float quad0 = 2.0f * fmaf(fmaf(d00, qd0, e0 * qd1), Ltq0, d10 * qd1 * Ltq1);
    const float quad1 = 2.0f * fmaf(fmaf(d01, qd0, e1 * qd1), Ltq0, d11 * qd1 * Ltq1);

    t0 = Hq0 + dHq0 + quad0 + g0;
    t1 = Hq1 + dHq1 + quad1 + g1;
}

__global__ void __launch_bounds__(256)
lnn_tau_kernel(const float* __restrict__ x,
               const float* __restrict__ W1, const float* __restrict__ b1,
               const float* __restrict__ W2, const float* __restrict__ b2,
               const float* __restrict__ W3, const float* __restrict__ b3,
               const float* __restrict__ W4, const float* __restrict__ b4,
               float* __restrict__ out, int n)
{
    // Hoist weights into registers once per thread.
    float w1[6][2], vb1[6], w2[2][6], vb2[2], w3[2][6], vb3[2], w4[6], vb4;
#pragma unroll
    for (int j = 0; j < 6; j++) {
        w1[j][0] = __ldg(W1 + 2 * j);
        w1[j][1] = __ldg(W1 + 2 * j + 1);
        vb1[j] = __ldg(b1 + j);
        w2[0][j] = __ldg(W2 + j);
        w2[1][j] = __ldg(W2 + 6 + j);
        w3[0][j] = __ldg(W3 + j);
        w3[1][j] = __ldg(W3 + 6 + j);
        w4[j] = __ldg(W4 + j);
    }
    vb2[0] = __ldg(b2 + 0); vb2[1] = __ldg(b2 + 1);
    vb3[0] = __ldg(b3 + 0); vb3[1] = __ldg(b3 + 1);
    vb4 = __ldg(b4);

    const int nq = n >> 2;                 // quads of 4 rows
    const int stride = gridDim.x * blockDim.x;

    for (int qi = blockIdx.x * blockDim.x + threadIdx.x; qi < nq; qi += stride) {
        const float4* xp = reinterpret_cast<const float4*>(x + (size_t)qi * 24);
        float4 v0 = xp[0], v1 = xp[1], v2 = xp[2], v3 = xp[3], v4 = xp[4], v5 = xp[5];

        float rows[4][6] = {
            { v0.x, v0.y, v0.z, v0.w, v1.x, v1.y },
            { v1.z, v1.w, v2.x, v2.y, v2.z, v2.w },
            { v3.x, v3.y, v3.z, v3.w, v4.x, v4.y },
            { v4.z, v4.w, v5.x, v5.y, v5.z, v5.w }
        };

        float o[8];
#pragma unroll
        for (int r = 0; r < 4; r++) {
            compute_row(rows[r], w1, vb1, w2, vb2, w3, vb3, w4, vb4,
                        o[2 * r], o[2 * r + 1]);
        }

        float4* op = reinterpret_cast<float4*>(out + (size_t)qi * 8);
        op[0] = make_float4(o[0], o[1], o[2], o[3]);
        op[1] = make_float4(o[4], o[5], o[6], o[7]);
    }

    // Tail rows (n % 4 != 0): handled scalar by the first few threads.
    const int rem = n & 3;
    if (rem) {
        int idx = blockIdx.x * blockDim.x + threadIdx.x;
        if (idx < rem) {
            int row = nq * 4 + idx;
            float in[6];
#pragma unroll
            for (int k = 0; k < 6; k++) in[k] = x[(size_t)row * 6 + k];
            float t0, t1;
            compute_row(in, w1, vb1, w2, vb2, w3, vb3, w4, vb4, t0, t1);
            out[(size_t)row * 2 + 0] = t0;
            out[(size_t)row * 2 + 1] = t1;
        }
    }
}

extern "C" void kernel_launch(void* const* d_in, const int* in_sizes, int n_in,
                              void* d_out, int out_size)
{
    const float* x  = (const float*)d_in[0];
    const float* W1 = (const float*)d_in[1];
    const float* b1 = (const float*)d_in[2];
    const float* W2 = (const float*)d_in[3];
    const float* b2 = (const float*)d_in[4];
    const float* W3 = (const float*)d_in[5];
    const float* b3 = (const float*)d_in[6];
    const float* W4 = (const float*)d_in[7];
    const float* b4 = (const float*)d_in[8];
    float* out = (float*)d_out;

    const int n = in_sizes[0] / 6;   // rows

    const int threads = 256;
    // grid-stride: enough blocks for full occupancy, weights amortized over iters
    int blocks = 148 * 4;
    lnn_tau_kernel<<<blocks, threads>>>(x, W1, b1, W2, b2, W3, b3, W4, b4, out, n);
}

// round 2
// speedup vs baseline: 1.1212x; 1.1212x over previous
#include <cuda_runtime.h>

#define EPS 0.001f
typedef unsigned long long u64;

// ---- packed f32x2 helpers (sm_100+) ----
__device__ __forceinline__ u64 pk2(float lo, float hi) {
    u64 r; asm("mov.b64 %0,{%1,%2};" : "=l"(r) : "f"(lo), "f"(hi)); return r;
}
__device__ __forceinline__ void upk2(u64 v, float& lo, float& hi) {
    asm("mov.b64 {%0,%1},%2;" : "=f"(lo), "=f"(hi) : "l"(v));
}
__device__ __forceinline__ u64 ffma2(u64 a, u64 b, u64 c) {
    u64 d; asm("fma.rn.f32x2 %0,%1,%2,%3;" : "=l"(d) : "l"(a), "l"(b), "l"(c)); return d;
}

struct Wts {
    u64 w1c0[3], w1c1[3], b1p[3];   // W1 col0/col1/b1, packed over j-pairs
    u64 w2p[6], w3p[6];             // (W2[0][j],W2[1][j]), (W3[0][j],W3[1][j])
    float w4[6];
    u64 b2p, b3p;
    float b4;
};

__device__ __forceinline__ void compute_row(
    const float in[6], const Wts& W,
    const float4* __restrict__ tabd, const float2* __restrict__ tabe,
    float& t0, float& t1)
{
    const float q0 = in[0], q1 = in[1];
    const float qd0 = in[2], qd1 = in[3];
    const float qdd0 = in[4], qdd1 = in[5];

    // z = W1 q + b1, packed over j-pairs
    const u64 q0p = pk2(q0, q0), q1p = pk2(q1, q1);
    float z[6];
#pragma unroll
    for (int p = 0; p < 3; p++) {
        u64 zp = ffma2(W.w1c0[p], q0p, ffma2(W.w1c1[p], q1p, W.b1p[p]));
        upk2(zp, z[2 * p], z[2 * p + 1]);
    }

    int mask = 0;
    float h[6];
#pragma unroll
    for (int j = 0; j < 6; j++) {
        h[j] = fmaxf(z[j], 0.0f);
        mask |= (int)(z[j] > 0.0f) << j;
    }

    // g=(g0,g1), s3=(s30,s31) packed over output index; lo scalar
    u64 gp = W.b2p, s3p = W.b3p;
    float lo = W.b4;
#pragma unroll
    for (int j = 0; j < 6; j++) {
        u64 hh = pk2(h[j], h[j]);
        gp  = ffma2(W.w2p[j], hh, gp);
        s3p = ffma2(W.w3p[j], hh, s3p);
        lo  = fmaf(W.w4[j], h[j], lo);
    }
    float g0, g1, s30, s31;
    upk2(gp, g0, g1);
    upk2(s3p, s30, s31);

    const float a = fmaxf(s30, 0.0f);
    const float b = fmaxf(s31, 0.0f);
    const float c = lo;
    const float m0 = (s30 > 0.0f) ? 1.0f : 0.0f;
    const float m1 = (s31 > 0.0f) ? 1.0f : 0.0f;

    // Jacobian sums via 64-entry mask table (exact same f32 sums)
    const float4 dv = tabd[mask];
    const float2 ev = tabe[mask];
    const float d00 = dv.x * m0, d01 = dv.y * m0;
    const float d10 = dv.z * m1, d11 = dv.w * m1;
    const float e0 = ev.x, e1 = ev.y;

    // time derivatives
    const float da = fmaf(d00, qd0, d01 * qd1);
    const float db = fmaf(d10, qd0, d11 * qd1);
    const float dc = fmaf(e0,  qd0, e1  * qd1);

    // H q_ddot = L^T (L q_ddot) + eps q_ddot
    const float Lq0 = a * qdd0;
    const float Lq1 = fmaf(c, qdd0, b * qdd1);
    const float Hq0 = fmaf(a, Lq0, fmaf(c, Lq1, EPS * qdd0));
    const float Hq1 = fmaf(b, Lq1, EPS * qdd1);

    // dH_dt terms
    const float dh01 = fmaf(a, dc, c * da);
    const float dHq0 = fmaf(2.0f * a * da, qd0, dh01 * qd1);
    const float dHq1 = fmaf(dh01, qd0, 2.0f * fmaf(c, dc, b * db) * qd1);

    // quad_i = 2 (B_i^T qd) . (L^T qd)
    const float Ltq0 = fmaf(a, qd0, c * qd1);
    const float Ltq1 = b * qd1;
    const float quad0 = 2.0f * fmaf(fmaf(d00, qd0, e0 * qd1), Ltq0, d10 * qd1 * Ltq1);
    const float quad1 = 2.0f * fmaf(fmaf(d01, qd0, e1 * qd1), Ltq0, d11 * qd1 * Ltq1);

    t0 = Hq0 + dHq0 + quad0 + g0;
    t1 = Hq1 + dHq1 + quad1 + g1;
}

__global__ void __launch_bounds__(128)
lnn_tau_kernel(const float* __restrict__ x,
               const float* __restrict__ W1, const float* __restrict__ b1,
               const float* __restrict__ W2, const float* __restrict__ b2,
               const float* __restrict__ W3, const float* __restrict__ b3,
               const float* __restrict__ W4, const float* __restrict__ b4,
               float* __restrict__ out, int n)
{
    __shared__ float4 tabd[64];
    __shared__ float2 tabe[64];

    // Build the 64-entry ReLU-mask Jacobian table (one warp's worth of work).
    if (threadIdx.x < 64) {
        const int m = threadIdx.x;
        float d00 = 0.f, d01 = 0.f, d10 = 0.f, d11 = 0.f, e0 = 0.f, e1 = 0.f;
#pragma unroll
        for (int j = 0; j < 6; j++) {
            if ((m >> j) & 1) {
                const float a0 = W1[2 * j], a1 = W1[2 * j + 1];
                const float w30 = W3[j], w31 = W3[6 + j], w4j = W4[j];
                d00 = fmaf(w30, a0, d00); d01 = fmaf(w30, a1, d01);
                d10 = fmaf(w31, a0, d10); d11 = fmaf(w31, a1, d11);
                e0  = fmaf(w4j, a0, e0);  e1  = fmaf(w4j, a1, e1);
            }
        }
        tabd[m] = make_float4(d00, d01, d10, d11);
        tabe[m] = make_float2(e0, e1);
    }

    // Hoist weights into packed registers.
    Wts W;
#pragma unroll
    for (int p = 0; p < 3; p++) {
        W.w1c0[p] = pk2(__ldg(W1 + 4 * p),     __ldg(W1 + 4 * p + 2));
        W.w1c1[p] = pk2(__ldg(W1 + 4 * p + 1), __ldg(W1 + 4 * p + 3));
        W.b1p[p]  = pk2(__ldg(b1 + 2 * p),     __ldg(b1 + 2 * p + 1));
    }
#pragma unroll
    for (int j = 0; j < 6; j++) {
        W.w2p[j] = pk2(__ldg(W2 + j), __ldg(W2 + 6 + j));
        W.w3p[j] = pk2(__ldg(W3 + j), __ldg(W3 + 6 + j));
        W.w4[j]  = __ldg(W4 + j);
    }
    W.b2p = pk2(__ldg(b2), __ldg(b2 + 1));
    W.b3p = pk2(__ldg(b3), __ldg(b3 + 1));
    W.b4  = __ldg(b4);

    __syncthreads();

    const int nq = n >> 2;  // quads of 4 rows
    const int stride = gridDim.x * blockDim.x;

    for (int qi = blockIdx.x * blockDim.x + threadIdx.x; qi < nq; qi += stride) {
        const float4* xp = reinterpret_cast<const float4*>(x + (size_t)qi * 24);
        float4 v0 = xp[0], v1 = xp[1], v2 = xp[2], v3 = xp[3], v4 = xp[4], v5 = xp[5];

        float rows[4][6] = {
            { v0.x, v0.y, v0.z, v0.w, v1.x, v1.y },
            { v1.z, v1.w, v2.x, v2.y, v2.z, v2.w },
            { v3.x, v3.y, v3.z, v3.w, v4.x, v4.y },
            { v4.z, v4.w, v5.x, v5.y, v5.z, v5.w }
        };

        float o[8];
#pragma unroll
        for (int r = 0; r < 4; r++)
            compute_row(rows[r], W, tabd, tabe, o[2 * r], o[2 * r + 1]);

        float4* op = reinterpret_cast<float4*>(out + (size_t)qi * 8);
        op[0] = make_float4(o[0], o[1], o[2], o[3]);
        op[1] = make_float4(o[4], o[5], o[6], o[7]);
    }

    // Tail (n % 4) — n is divisible by 4 in this problem, kept for safety.
    const int rem = n & 3;
    if (rem) {
        int idx = blockIdx.x * blockDim.x + threadIdx.x;
        if (idx < rem) {
            int row = nq * 4 + idx;
            float in[6];
#pragma unroll
            for (int k = 0; k < 6; k++) in[k] = x[(size_t)row * 6 + k];
            float t0, t1;
            compute_row(in, W, tabd, tabe, t0, t1);
            out[(size_t)row * 2 + 0] = t0;
            out[(size_t)row * 2 + 1] = t1;
        }
    }
}

extern "C" void kernel_launch(void* const* d_in, const int* in_sizes, int n_in,
                              void* d_out, int out_size)
{
    const float* x  = (const float*)d_in[0];
    const float* W1 = (const float*)d_in[1];
    const float* b1 = (const float*)d_in[2];
    const float* W2 = (const float*)d_in[3];
    const float* b2 = (const float*)d_in[4];
    const float* W3 = (const float*)d_in[5];
    const float* b3 = (const float*)d_in[6];
    const float* W4 = (const float*)d_in[7];
    const float* b4 = (const float*)d_in[8];
    float* out = (float*)d_out;

    const int n = in_sizes[0] / 6;   // rows

    const int threads = 128;
    const int blocks = 148 * 7;      // ~66 regs -> 7 blocks/SM resident, grid-stride
    lnn_tau_kernel<<<blocks, threads>>>(x, W1, b1, W2, b2, W3, b3, W4, b4, out, n);
}